// round 4
// baseline (speedup 1.0000x reference)
#include <cuda_runtime.h>
#include <math.h>
#include <stdint.h>

#define BATCH 4096
#define KPTS  64
#define NMAT  65
#define GAMMA_C 0.5f
#define R2_POS  0.36f   /* 0.6^2  */
#define R2_NEG  1.44f   /* 1.2^2  */

__device__ double       g_acc;
__device__ unsigned int g_flags;   // bit1: masks are f32, bit0: masks are u8, else i32

__global__ void zero_kernel() {
    g_acc   = 0.0;
    g_flags = 0u;
}

// Classify mask dtype by scanning (element_count/4) 32-bit words — valid in every
// candidate layout. u8 masks (0/1 bytes) give packed words like 0x01010101 (>1);
// f32 masks give 0x3F800000; i32 masks give only 0/1.
__global__ void detect_kernel(const unsigned int* __restrict__ m, int nwords) {
    unsigned f = 0;
    for (int i = blockIdx.x * blockDim.x + threadIdx.x; i < nwords;
         i += gridDim.x * blockDim.x) {
        unsigned v = m[i];
        if (v == 0x3F800000u)      f |= 2u;
        else if (v > 1u)           f |= 1u;
    }
    if (f) atomicOr(&g_flags, f);
}

__device__ __forceinline__ bool read_mask(const void* p, size_t idx, unsigned mode) {
    if (mode & 2u) return ((const float*)p)[idx] != 0.0f;
    if (mode & 1u) return ((const uint8_t*)p)[idx] != 0;
    return ((const int*)p)[idx] != 0;
}

__global__ __launch_bounds__(256, 8) void loss_kernel(
    const float* __restrict__ pos_pts,   // (B,K,3)
    const float* __restrict__ anc_pts,   // (B,K,3)
    const void*  __restrict__ pos_m,     // (B,K) bool-ish
    const void*  __restrict__ anc_m,     // (B,K) bool-ish
    const float* __restrict__ ms,        // (B,N,N)
    const float* __restrict__ T)         // (4,4)
{
    __shared__ float sm[NMAT][67];       // padded: column stride 67 -> conflict-free
    __shared__ float px[KPTS], py[KPTS], pz[KPTS], pn[KPTS];
    __shared__ float ax[KPTS], ay[KPTS], az[KPTS], an[KPTS];
    __shared__ unsigned char s_pm[KPTS], s_am[KPTS];
    __shared__ float warp_sum[8];

    const int b    = blockIdx.x;
    const int tid  = threadIdx.x;
    const int lane = tid & 31;
    const int w    = tid >> 5;

    // ---- load the 65x65 score tile (coalesced, single DRAM pass) ----
    const float* msb = ms + (size_t)b * NMAT * NMAT;
    #pragma unroll
    for (int it = 0; it < 17; ++it) {
        int i = tid + it * 256;
        if (i < NMAT * NMAT) sm[i / NMAT][i % NMAT] = msb[i];
    }

    const unsigned mode = g_flags;

    // ---- load points / transform anchors / masks ----
    if (tid < 64) {
        const float* p = pos_pts + ((size_t)b * KPTS + tid) * 3;
        float x = p[0], y = p[1], z = p[2];
        px[tid] = x; py[tid] = y; pz[tid] = z;
        pn[tid] = x * x + y * y + z * z;
    } else if (tid < 128) {
        int k = tid - 64;
        const float* p = anc_pts + ((size_t)b * KPTS + k) * 3;
        float x = p[0], y = p[1], z = p[2];
        float X = T[0] * x + T[1] * y + T[2]  * z + T[3];
        float Y = T[4] * x + T[5] * y + T[6]  * z + T[7];
        float Z = T[8] * x + T[9] * y + T[10] * z + T[11];
        ax[k] = X; ay[k] = Y; az[k] = Z;
        an[k] = X * X + Y * Y + Z * Z;
    } else if (tid < 192) {
        int k = tid - 128;
        s_pm[k] = read_mask(pos_m, (size_t)b * KPTS + k, mode) ? 1 : 0;
    } else {
        int k = tid - 192;
        s_am[k] = read_mask(anc_m, (size_t)b * KPTS + k, mode) ? 1 : 0;
    }
    __syncthreads();

    float acc = 0.0f;   // only lane 0 of each warp accumulates

    // ================= row pass (loss1): rows 0..63, cols 0..64 =================
    for (int i = w; i < KPTS; i += 8) {
        const bool  pmk = s_pm[i];
        const float Xi = px[i], Yi = py[i], Zi = pz[i], Ni = pn[i];

        const int j0 = lane, j1 = lane + 32;
        const float m0 = sm[i][j0], m1 = sm[i][j1];
        // mimic reference: x2 - 2xy + y2
        float d0 = (Ni - 2.0f * (Xi * ax[j0] + Yi * ay[j0] + Zi * az[j0])) + an[j0];
        float d1 = (Ni - 2.0f * (Xi * ax[j1] + Yi * ay[j1] + Zi * az[j1])) + an[j1];
        const bool c0 = (d0 < R2_POS) && pmk && s_am[j0];
        const bool c1 = (d1 < R2_POS) && pmk && s_am[j1];
        const bool n0 = d0 > R2_NEG;
        const bool n1 = d1 > R2_NEG;

        int   cnt  = (int)c0 + (int)c1;
        float psum = (c0 ? -m0 : 0.0f) + (c1 ? -m1 : 0.0f);
        #pragma unroll
        for (int o = 16; o; o >>= 1) {
            cnt  += __shfl_xor_sync(0xFFFFFFFFu, cnt,  o);
            psum += __shfl_xor_sync(0xFFFFFFFFu, psum, o);
        }
        const float me = sm[i][KPTS];                  // slack column
        const float ps = cnt ? psum / (float)cnt : -me;

        float s = (n0 ? fmaxf(ps + m0 + GAMMA_C, 0.0f) : 0.0f)
                + (n1 ? fmaxf(ps + m1 + GAMMA_C, 0.0f) : 0.0f);
        #pragma unroll
        for (int o = 16; o; o >>= 1) s += __shfl_xor_sync(0xFFFFFFFFu, s, o);
        if (cnt) s += fmaxf(ps + me + GAMMA_C, 0.0f);  // nm[i][64] = !row_none

        if (lane == 0) acc += logf(s + 1.0f);
    }

    // ================= column pass (loss2): cols 0..63, rows 0..64 =================
    for (int j = w; j < KPTS; j += 8) {
        const bool  amk = s_am[j];
        const float Xj = ax[j], Yj = ay[j], Zj = az[j], Nj = an[j];

        const int i0 = lane, i1 = lane + 32;
        const float m0 = sm[i0][j], m1 = sm[i1][j];   // stride-67 -> conflict-free
        float d0 = (pn[i0] - 2.0f * (px[i0] * Xj + py[i0] * Yj + pz[i0] * Zj)) + Nj;
        float d1 = (pn[i1] - 2.0f * (px[i1] * Xj + py[i1] * Yj + pz[i1] * Zj)) + Nj;
        const bool c0 = (d0 < R2_POS) && amk && s_pm[i0];
        const bool c1 = (d1 < R2_POS) && amk && s_pm[i1];
        const bool n0 = d0 > R2_NEG;
        const bool n1 = d1 > R2_NEG;

        int   cnt  = (int)c0 + (int)c1;
        float psum = (c0 ? -m0 : 0.0f) + (c1 ? -m1 : 0.0f);
        #pragma unroll
        for (int o = 16; o; o >>= 1) {
            cnt  += __shfl_xor_sync(0xFFFFFFFFu, cnt,  o);
            psum += __shfl_xor_sync(0xFFFFFFFFu, psum, o);
        }
        const float me = sm[KPTS][j];                  // slack row
        const float ps = cnt ? psum / (float)cnt : -me;

        float s = (n0 ? fmaxf(ps + m0 + GAMMA_C, 0.0f) : 0.0f)
                + (n1 ? fmaxf(ps + m1 + GAMMA_C, 0.0f) : 0.0f);
        #pragma unroll
        for (int o = 16; o; o >>= 1) s += __shfl_xor_sync(0xFFFFFFFFu, s, o);
        if (cnt) s += fmaxf(ps + me + GAMMA_C, 0.0f);  // nmc[64][j] = !col_none

        if (lane == 0) acc += logf(s + 1.0f);
    }

    // ---- block reduce + global accumulate ----
    if (lane == 0) warp_sum[w] = acc;
    __syncthreads();
    if (tid == 0) {
        float tot = 0.0f;
        #pragma unroll
        for (int i = 0; i < 8; ++i) tot += warp_sum[i];
        atomicAdd(&g_acc, (double)tot);
    }
}

__global__ void finalize_kernel(float* out) {
    // loss = (sum1/(B*K) + sum2/(B*K)) / 2 = total / (2*B*K)
    out[0] = (float)(g_acc * (1.0 / (2.0 * (double)BATCH * (double)KPTS)));
}

extern "C" void kernel_launch(void* const* d_in, const int* in_sizes, int n_in,
                              void* d_out, int out_size) {
    const float* pos_pts = (const float*)d_in[0];
    const float* anc_pts = (const float*)d_in[1];
    const void*  pos_m   = d_in[2];
    const void*  anc_m   = d_in[3];
    const float* ms      = (const float*)d_in[4];
    const float* T       = (const float*)d_in[5];

    zero_kernel<<<1, 1>>>();
    int nwords = in_sizes[2] / 4;            // safe lower bound in all layouts
    if (nwords > 0)
        detect_kernel<<<64, 256>>>((const unsigned int*)pos_m, nwords);
    loss_kernel<<<BATCH, 256>>>(pos_pts, anc_pts, pos_m, anc_m, ms, T);
    finalize_kernel<<<1, 1>>>((float*)d_out);
}

// round 5
// speedup vs baseline: 1.8471x; 1.8471x over previous
#include <cuda_runtime.h>
#include <math.h>
#include <stdint.h>

#define BATCH 4096
#define KPTS  64
#define NMAT  65
#define GAMMA_C 0.5f
#define R2_POS  0.36f   /* 0.6^2  */
#define R2_NEG  1.44f   /* 1.2^2  */

__device__ unsigned int g_flags;            // bit1: f32 masks, bit0: u8 masks, else i32 (monotone)
__device__ float        g_partial[BATCH];   // per-block partial sums
__device__ unsigned int g_done;             // completion counter (self-resetting)

// Classify mask dtype by scanning (element_count/4) 32-bit words — valid in every
// candidate layout. u8 masks give packed words like 0x01010101 (>1); f32 masks
// give 0x3F800000; i32 masks give only 0/1. Idempotent across graph replays.
__global__ void detect_kernel(const unsigned int* __restrict__ m, int nwords) {
    unsigned f = 0;
    for (int i = blockIdx.x * blockDim.x + threadIdx.x; i < nwords;
         i += gridDim.x * blockDim.x) {
        unsigned v = m[i];
        if (v == 0x3F800000u) f |= 2u;
        else if (v > 1u)      f |= 1u;
    }
    if (f) atomicOr(&g_flags, f);
}

__device__ __forceinline__ bool read_mask(const void* p, size_t idx, unsigned mode) {
    if (mode & 2u) return ((const float*)p)[idx] != 0.0f;
    if (mode & 1u) return ((const uint8_t*)p)[idx] != 0;
    return ((const int*)p)[idx] != 0;
}

__global__ __launch_bounds__(256, 4) void loss_kernel(
    const float* __restrict__ pos_pts,   // (B,K,3)
    const float* __restrict__ anc_pts,   // (B,K,3)
    const void*  __restrict__ pos_m,     // (B,K)
    const void*  __restrict__ anc_m,     // (B,K)
    const float* __restrict__ ms,        // (B,N,N)
    const float* __restrict__ T,         // (4,4)
    float*       __restrict__ out)
{
    __shared__ float sm[NMAT][67];       // stride 67: conflict-free rows AND columns
    __shared__ float px[KPTS], py_[KPTS], pz[KPTS], pn[KPTS];
    __shared__ float ax[KPTS], ay[KPTS], az[KPTS], an[KPTS];
    __shared__ unsigned char s_pm[KPTS], s_am[KPTS];
    __shared__ unsigned int  corr_lo[KPTS], corr_hi[KPTS], neg_lo[KPTS], neg_hi[KPTS];
    __shared__ float  comb_p[128][2];
    __shared__ int    comb_c[128][2];
    __shared__ float  comb_s[128][2];
    __shared__ float  warp_sum[8];
    __shared__ double dsum[8];
    __shared__ int    s_last;

    const int b    = blockIdx.x;
    const int tid  = threadIdx.x;
    const int lane = tid & 31;
    const int w    = tid >> 5;

    // ---- load the 65x65 score tile (coalesced, single DRAM pass) ----
    const float* msb = ms + (size_t)b * NMAT * NMAT;
    #pragma unroll
    for (int it = 0; it < 17; ++it) {
        int i = tid + it * 256;
        if (i < NMAT * NMAT) sm[i / NMAT][i % NMAT] = msb[i];
    }

    const unsigned mode = g_flags;

    // ---- load points / transform anchors / masks ----
    if (tid < 64) {
        const float* p = pos_pts + ((size_t)b * KPTS + tid) * 3;
        float x = p[0], y = p[1], z = p[2];
        px[tid] = x; py_[tid] = y; pz[tid] = z;
        pn[tid] = x * x + y * y + z * z;
    } else if (tid < 128) {
        int k = tid - 64;
        const float* p = anc_pts + ((size_t)b * KPTS + k) * 3;
        float x = p[0], y = p[1], z = p[2];
        float X = T[0] * x + T[1] * y + T[2]  * z + T[3];
        float Y = T[4] * x + T[5] * y + T[6]  * z + T[7];
        float Z = T[8] * x + T[9] * y + T[10] * z + T[11];
        ax[k] = X; ay[k] = Y; az[k] = Z;
        an[k] = X * X + Y * Y + Z * Z;
    } else if (tid < 192) {
        int k = tid - 128;
        s_pm[k] = read_mask(pos_m, (size_t)b * KPTS + k, mode) ? 1 : 0;
    } else {
        int k = tid - 192;
        s_am[k] = read_mask(anc_m, (size_t)b * KPTS + k, mode) ? 1 : 0;
    }
    __syncthreads();

    // ================= Phase A: geometry -> packed corr/neg bitmasks ==========
    // Warp w handles rows [w*8, w*8+8). Lane handles cols j0=lane, j1=lane+32.
    {
        const int j0 = lane, j1 = lane + 32;
        const float ax0 = ax[j0], ay0 = ay[j0], az0 = az[j0], an0 = an[j0];
        const float ax1 = ax[j1], ay1 = ay[j1], az1 = az[j1], an1 = an[j1];
        const bool  am0 = s_am[j0], am1 = s_am[j1];
        #pragma unroll
        for (int r = 0; r < 8; ++r) {
            const int   i  = w * 8 + r;
            const float Xi = px[i], Yi = py_[i], Zi = pz[i], Ni = pn[i];
            const bool  pmk = s_pm[i];
            // mimic reference: (x2 - 2xy) + y2
            float d0 = (Ni - 2.0f * (Xi * ax0 + Yi * ay0 + Zi * az0)) + an0;
            float d1 = (Ni - 2.0f * (Xi * ax1 + Yi * ay1 + Zi * az1)) + an1;
            unsigned c_lo = __ballot_sync(0xFFFFFFFFu, (d0 < R2_POS) && pmk && am0);
            unsigned c_hi = __ballot_sync(0xFFFFFFFFu, (d1 < R2_POS) && pmk && am1);
            unsigned n_lo = __ballot_sync(0xFFFFFFFFu, d0 > R2_NEG);
            unsigned n_hi = __ballot_sync(0xFFFFFFFFu, d1 > R2_NEG);
            if (lane == 0) {
                corr_lo[i] = c_lo; corr_hi[i] = c_hi;
                neg_lo[i]  = n_lo; neg_hi[i]  = n_hi;
            }
        }
    }
    __syncthreads();

    // ================= Phase B: row loss (pass 0) + col loss (pass 1) =========
    // pass = tid>>7 (warp-aligned). Within a pass: idx = row i (or col j),
    // h = which half of the 64-wide reduction this thread covers.
    const int pass = tid >> 7;
    const int rr   = tid & 127;
    const int idx  = rr & 63;
    const int h    = rr >> 6;
    const int g    = (pass << 6) | idx;

    float psum = 0.0f;
    int   cnt  = 0;
    float slack_m;

    if (pass == 0) {
        const unsigned cw  = h ? corr_hi[idx] : corr_lo[idx];
        const float*   row = &sm[idx][h * 32];
        cnt = __popc(cw);
        #pragma unroll
        for (int jj = 0; jj < 32; ++jj)
            if ((cw >> jj) & 1u) psum -= row[jj];
        slack_m = sm[idx][KPTS];
    } else {
        const unsigned shift = idx & 31;
        const unsigned* cbase = (idx < 32) ? corr_lo : corr_hi;
        #pragma unroll
        for (int kk = 0; kk < 32; ++kk) {
            const int i = h * 32 + kk;
            if ((cbase[i] >> shift) & 1u) { psum -= sm[i][idx]; ++cnt; }
        }
        slack_m = sm[KPTS][idx];
    }
    comb_p[g][h] = psum;
    comb_c[g][h] = cnt;
    __syncthreads();

    const float psum_t = comb_p[g][0] + comb_p[g][1];
    const int   cnt_t  = comb_c[g][0] + comb_c[g][1];
    const float ps     = cnt_t ? psum_t / (float)cnt_t : -slack_m;
    const float base   = ps + GAMMA_C;

    float s = 0.0f;
    if (pass == 0) {
        const unsigned nw  = h ? neg_hi[idx] : neg_lo[idx];
        const float*   row = &sm[idx][h * 32];
        #pragma unroll
        for (int jj = 0; jj < 32; ++jj)
            if ((nw >> jj) & 1u) s += fmaxf(base + row[jj], 0.0f);
    } else {
        const unsigned shift = idx & 31;
        const unsigned* nbase = (idx < 32) ? neg_lo : neg_hi;
        #pragma unroll
        for (int kk = 0; kk < 32; ++kk) {
            const int i = h * 32 + kk;
            if ((nbase[i] >> shift) & 1u) s += fmaxf(base + sm[i][idx], 0.0f);
        }
    }
    comb_s[g][h] = s;
    __syncthreads();

    float acc = 0.0f;
    if (h == 0) {
        float st = comb_s[g][0] + comb_s[g][1];
        if (cnt_t) st += fmaxf(base + slack_m, 0.0f);   // slack entry: !row_none / !col_none
        acc = logf(st + 1.0f);
    }

    // ---- block reduce ----
    #pragma unroll
    for (int o = 16; o; o >>= 1) acc += __shfl_xor_sync(0xFFFFFFFFu, acc, o);
    if (lane == 0) warp_sum[w] = acc;
    __syncthreads();
    if (tid == 0) {
        float tot = 0.0f;
        #pragma unroll
        for (int i = 0; i < 8; ++i) tot += warp_sum[i];
        g_partial[b] = tot;
        __threadfence();
        unsigned prev = atomicAdd(&g_done, 1u);
        s_last = (prev == BATCH - 1) ? 1 : 0;
    }
    __syncthreads();

    // ---- last block finalizes (saves a separate launch) ----
    if (s_last) {
        __threadfence();
        double d = 0.0;
        for (int i = tid; i < BATCH; i += 256) d += (double)g_partial[i];
        #pragma unroll
        for (int o = 16; o; o >>= 1) d += __shfl_xor_sync(0xFFFFFFFFu, d, o);
        if (lane == 0) dsum[w] = d;
        __syncthreads();
        if (tid == 0) {
            double t = 0.0;
            #pragma unroll
            for (int i = 0; i < 8; ++i) t += dsum[i];
            out[0] = (float)(t * (1.0 / (2.0 * (double)BATCH * (double)KPTS)));
            g_done = 0u;   // self-reset -> graph-replay deterministic
        }
    }
}

extern "C" void kernel_launch(void* const* d_in, const int* in_sizes, int n_in,
                              void* d_out, int out_size) {
    const float* pos_pts = (const float*)d_in[0];
    const float* anc_pts = (const float*)d_in[1];
    const void*  pos_m   = d_in[2];
    const void*  anc_m   = d_in[3];
    const float* ms      = (const float*)d_in[4];
    const float* T       = (const float*)d_in[5];

    int nwords = in_sizes[2] / 4;            // safe lower bound in all layouts
    if (nwords > 0)
        detect_kernel<<<64, 256>>>((const unsigned int*)pos_m, nwords);
    loss_kernel<<<BATCH, 256>>>(pos_pts, anc_pts, pos_m, anc_m, ms, T, (float*)d_out);
}

// round 7
// speedup vs baseline: 2.0929x; 1.1331x over previous
#include <cuda_runtime.h>
#include <math.h>
#include <stdint.h>

#define BATCH 4096
#define KPTS  64
#define NMAT  65
#define TILE  (NMAT * NMAT)   /* 4225 */
#define GAMMA_C 0.5f
#define R2_POS  0.36f   /* 0.6^2  */
#define R2_NEG  1.44f   /* 1.2^2  */

__device__ float        g_partial[BATCH];   // per-block partial sums
__device__ unsigned int g_done;             // completion counter (self-resetting)

__device__ __forceinline__ bool read_mask(const void* p, size_t idx, unsigned mode) {
    if (mode & 2u) return ((const float*)p)[idx] != 0.0f;
    if (mode & 1u) return ((const uint8_t*)p)[idx] != 0;
    return ((const int*)p)[idx] != 0;
}

__global__ __launch_bounds__(256, 5) void loss_kernel(
    const float* __restrict__ pos_pts,   // (B,K,3)
    const float* __restrict__ anc_pts,   // (B,K,3)
    const void*  __restrict__ pos_m,     // (B,K) bool-ish
    const void*  __restrict__ anc_m,     // (B,K)
    const float* __restrict__ ms,        // (B,N,N)
    const float* __restrict__ T,         // (4,4)
    float*       __restrict__ out)
{
    __shared__ float sm[TILE];           // flat, stride 65 (odd) -> rows AND cols conflict-free
    __shared__ float px[KPTS], py_[KPTS], pz[KPTS], pn[KPTS];
    __shared__ float ax[KPTS], ay[KPTS], az[KPTS], an[KPTS];
    __shared__ unsigned char s_pm[KPTS], s_am[KPTS];
    __shared__ unsigned int  corr_lo[KPTS], corr_hi[KPTS], neg_lo[KPTS], neg_hi[KPTS];
    __shared__ float  comb_p[128][2];
    __shared__ int    comb_c[128][2];
    __shared__ float  comb_s[128][2];
    __shared__ float  warp_sum[8];
    __shared__ double dsum[8];
    __shared__ int    s_last;

    const int b    = blockIdx.x;
    const int tid  = threadIdx.x;
    const int lane = tid & 31;
    const int w    = tid >> 5;

    // ---- flat tile copy: no div/mod, coalesced, single DRAM pass ----
    const float* msb = ms + (size_t)b * TILE;
    #pragma unroll
    for (int it = 0; it < 17; ++it) {
        int i = tid + it * 256;
        if (i < TILE) sm[i] = msb[i];
    }

    // ---- in-block mask dtype detection on a fixed 4KB window (L2-broadcast).
    // u8 masks give packed words >1 (e.g. 0x01010101); f32 gives 0x3F800000;
    // i32 gives only 0/1. Window = 1024 words, always within the smallest layout.
    unsigned f = 0;
    {
        const unsigned int* mw = (const unsigned int*)pos_m;
        #pragma unroll
        for (int it = 0; it < 4; ++it) {
            unsigned v = mw[tid + it * 256];
            if (v == 0x3F800000u) f |= 2u;
            else if (v > 1u)      f |= 1u;
        }
    }
    const unsigned mode = (unsigned)__syncthreads_or((int)f);

    // ---- points / transformed anchors / masks ----
    if (tid < 64) {
        const float* p = pos_pts + ((size_t)b * KPTS + tid) * 3;
        float x = p[0], y = p[1], z = p[2];
        px[tid] = x; py_[tid] = y; pz[tid] = z;
        pn[tid] = x * x + y * y + z * z;
    } else if (tid < 128) {
        int k = tid - 64;
        const float* p = anc_pts + ((size_t)b * KPTS + k) * 3;
        float x = p[0], y = p[1], z = p[2];
        float X = T[0] * x + T[1] * y + T[2]  * z + T[3];
        float Y = T[4] * x + T[5] * y + T[6]  * z + T[7];
        float Z = T[8] * x + T[9] * y + T[10] * z + T[11];
        ax[k] = X; ay[k] = Y; az[k] = Z;
        an[k] = X * X + Y * Y + Z * Z;
    } else if (tid < 192) {
        int k = tid - 128;
        s_pm[k] = read_mask(pos_m, (size_t)b * KPTS + k, mode) ? 1 : 0;
    } else {
        int k = tid - 192;
        s_am[k] = read_mask(anc_m, (size_t)b * KPTS + k, mode) ? 1 : 0;
    }
    __syncthreads();

    // ================= Phase A: geometry -> packed corr/neg bitmasks ==========
    {
        const int j0 = lane, j1 = lane + 32;
        const float ax0 = ax[j0], ay0 = ay[j0], az0 = az[j0], an0 = an[j0];
        const float ax1 = ax[j1], ay1 = ay[j1], az1 = az[j1], an1 = an[j1];
        const bool  am0 = s_am[j0], am1 = s_am[j1];
        #pragma unroll
        for (int r = 0; r < 8; ++r) {
            const int   i  = w * 8 + r;
            const float Xi = px[i], Yi = py_[i], Zi = pz[i], Ni = pn[i];
            const bool  pmk = s_pm[i];
            // mimic reference: (x2 - 2xy) + y2
            float d0 = (Ni - 2.0f * (Xi * ax0 + Yi * ay0 + Zi * az0)) + an0;
            float d1 = (Ni - 2.0f * (Xi * ax1 + Yi * ay1 + Zi * az1)) + an1;
            unsigned c_lo = __ballot_sync(0xFFFFFFFFu, (d0 < R2_POS) && pmk && am0);
            unsigned c_hi = __ballot_sync(0xFFFFFFFFu, (d1 < R2_POS) && pmk && am1);
            unsigned n_lo = __ballot_sync(0xFFFFFFFFu, d0 > R2_NEG);
            unsigned n_hi = __ballot_sync(0xFFFFFFFFu, d1 > R2_NEG);
            if (lane == 0) {
                corr_lo[i] = c_lo; corr_hi[i] = c_hi;
                neg_lo[i]  = n_lo; neg_hi[i]  = n_hi;
            }
        }
    }
    __syncthreads();

    // ================= Phase B: row loss (pass 0) + col loss (pass 1) =========
    const int pass = tid >> 7;
    const int rr   = tid & 127;
    const int idx  = rr & 63;
    const int h    = rr >> 6;
    const int g    = (pass << 6) | idx;

    float psA = 0.0f, psB = 0.0f;
    int   cnt = 0;
    float slack_m;

    if (pass == 0) {
        const unsigned cw  = h ? corr_hi[idx] : corr_lo[idx];
        const float*   row = &sm[idx * NMAT + h * 32];
        cnt = __popc(cw);
        #pragma unroll
        for (int jj = 0; jj < 16; ++jj) {
            if ((cw >> jj)        & 1u) psA -= row[jj];
            if ((cw >> (jj + 16)) & 1u) psB -= row[jj + 16];
        }
        slack_m = sm[idx * NMAT + KPTS];
    } else {
        const unsigned shift = idx & 31;
        const unsigned* cbase = (idx < 32) ? corr_lo : corr_hi;
        const float*    colp  = &sm[h * 32 * NMAT + idx];
        int cA = 0, cB = 0;
        #pragma unroll
        for (int kk = 0; kk < 16; ++kk) {
            const int i0 = h * 32 + kk, i1 = i0 + 16;
            if ((cbase[i0] >> shift) & 1u) { psA -= colp[kk * NMAT];        ++cA; }
            if ((cbase[i1] >> shift) & 1u) { psB -= colp[(kk + 16) * NMAT]; ++cB; }
        }
        cnt = cA + cB;
        slack_m = sm[KPTS * NMAT + idx];
    }
    comb_p[g][h] = psA + psB;
    comb_c[g][h] = cnt;
    __syncthreads();

    const float psum_t = comb_p[g][0] + comb_p[g][1];
    const int   cnt_t  = comb_c[g][0] + comb_c[g][1];
    const float ps     = cnt_t ? psum_t / (float)cnt_t : -slack_m;
    const float base   = ps + GAMMA_C;

    float sA = 0.0f, sB = 0.0f;
    if (pass == 0) {
        const unsigned nw  = h ? neg_hi[idx] : neg_lo[idx];
        const float*   row = &sm[idx * NMAT + h * 32];
        #pragma unroll
        for (int jj = 0; jj < 16; ++jj) {
            if ((nw >> jj)        & 1u) sA += fmaxf(base + row[jj],      0.0f);
            if ((nw >> (jj + 16)) & 1u) sB += fmaxf(base + row[jj + 16], 0.0f);
        }
    } else {
        const unsigned shift = idx & 31;
        const unsigned* nbase = (idx < 32) ? neg_lo : neg_hi;
        const float*    colp  = &sm[h * 32 * NMAT + idx];
        #pragma unroll
        for (int kk = 0; kk < 16; ++kk) {
            const int i0 = h * 32 + kk, i1 = i0 + 16;
            if ((nbase[i0] >> shift) & 1u) sA += fmaxf(base + colp[kk * NMAT],        0.0f);
            if ((nbase[i1] >> shift) & 1u) sB += fmaxf(base + colp[(kk + 16) * NMAT], 0.0f);
        }
    }
    comb_s[g][h] = sA + sB;
    __syncthreads();

    float acc = 0.0f;
    if (h == 0) {
        float st = comb_s[g][0] + comb_s[g][1];
        if (cnt_t) st += fmaxf(base + slack_m, 0.0f);   // slack entry: !row_none / !col_none
        acc = logf(st + 1.0f);
    }

    // ---- block reduce ----
    #pragma unroll
    for (int o = 16; o; o >>= 1) acc += __shfl_xor_sync(0xFFFFFFFFu, acc, o);
    if (lane == 0) warp_sum[w] = acc;
    __syncthreads();
    if (tid == 0) {
        float tot = 0.0f;
        #pragma unroll
        for (int i = 0; i < 8; ++i) tot += warp_sum[i];
        g_partial[b] = tot;
        __threadfence();
        unsigned prev = atomicAdd(&g_done, 1u);
        s_last = (prev == BATCH - 1) ? 1 : 0;
    }
    __syncthreads();

    // ---- last block finalizes (no extra launch) ----
    if (s_last) {
        __threadfence();
        double d = 0.0;
        for (int i = tid; i < BATCH; i += 256) d += (double)g_partial[i];
        #pragma unroll
        for (int o = 16; o; o >>= 1) d += __shfl_xor_sync(0xFFFFFFFFu, d, o);
        if (lane == 0) dsum[w] = d;
        __syncthreads();
        if (tid == 0) {
            double t = 0.0;
            #pragma unroll
            for (int i = 0; i < 8; ++i) t += dsum[i];
            out[0] = (float)(t * (1.0 / (2.0 * (double)BATCH * (double)KPTS)));
            g_done = 0u;   // self-reset -> graph-replay deterministic
        }
    }
}

extern "C" void kernel_launch(void* const* d_in, const int* in_sizes, int n_in,
                              void* d_out, int out_size) {
    const float* pos_pts = (const float*)d_in[0];
    const float* anc_pts = (const float*)d_in[1];
    const void*  pos_m   = d_in[2];
    const void*  anc_m   = d_in[3];
    const float* ms      = (const float*)d_in[4];
    const float* T       = (const float*)d_in[5];

    loss_kernel<<<BATCH, 256>>>(pos_pts, anc_pts, pos_m, anc_m, ms, T, (float*)d_out);
}